// round 15
// baseline (speedup 1.0000x reference)
#include <cuda_runtime.h>
#include <cuda_fp16.h>
#include <math.h>

// Persistent-kernel LSTM decoder. B=64, H=1024, L=2, T=128.
// 128 CTAs (1/SM), 256 threads (8 warps). warp=(ks,m2) 32x32 tile over
// k16s {ks,ks+4}; release-atomic grid barrier; R11/R14 epilogue
// (compile-time register indexing).
// R14 base: activation identity -- part-A h == previous part-B x, held in
// 8 persistent SMEM slots; Whh streamed; t==0 part A skipped.
// R15: prefetch depth 3 -- W ring 4 slots, prologues stage chunks {0,1,2},
// in-loop stage kc+3, cp.async.wait_group 2. Fill (~700cyc) now has ~1050cyc
// of compute to hide behind (was ~700 with zero slack).

#define BATCH   64
#define HID     1024
#define TSTEPS  128
#define NCTA    128
#define THREADS 256
#define SA      136    // act slot row stride (halfs)
#define SW      136    // streamed weight row stride (halfs)
#define KC      128    // K chunk
#define NKC     8      // chunks per matrix
#define NX4(s)  (((s) + 1) & 3)

// ---------------- device globals (pre-permuted fp16 weights + state) -------
__device__ __half g_Wst[2 * NCTA * 40 * HID];     // [l][cta][40 rows][k]: 32 Wih + 8 FC
__device__ __half g_Whh_p[2 * NCTA * 32 * HID];   // [l][cta][32][k] recurrent
__device__ __half g_hbuf[4 * BATCH * HID];        // [l*2+parity][b][h]
__device__ __half g_x0[BATCH * HID];
__device__ unsigned g_bar;

// ---------------- small asm helpers ---------------------------------------
__device__ __forceinline__ unsigned sptr(const void* p) {
    return (unsigned)__cvta_generic_to_shared(p);
}
__device__ __forceinline__ void cp16(void* s, const void* g) {      // weights (.ca)
    asm volatile("cp.async.ca.shared.global [%0], [%1], 16;" :: "r"(sptr(s)), "l"(g));
}
__device__ __forceinline__ void cp16cg(void* s, const void* g) {    // acts (.cg)
    asm volatile("cp.async.cg.shared.global [%0], [%1], 16;" :: "r"(sptr(s)), "l"(g));
}
__device__ __forceinline__ void cp_commit() {
    asm volatile("cp.async.commit_group;");
}
template<int N> __device__ __forceinline__ void cp_wait() {
    asm volatile("cp.async.wait_group %0;" :: "n"(N));
}
__device__ __forceinline__ void ldsm_x4(unsigned &r0, unsigned &r1, unsigned &r2, unsigned &r3, unsigned a) {
    asm volatile("ldmatrix.sync.aligned.m8n8.x4.shared.b16 {%0,%1,%2,%3}, [%4];"
                 : "=r"(r0), "=r"(r1), "=r"(r2), "=r"(r3) : "r"(a));
}
__device__ __forceinline__ void ldsm_x2(unsigned &r0, unsigned &r1, unsigned a) {
    asm volatile("ldmatrix.sync.aligned.m8n8.x2.shared.b16 {%0,%1}, [%2];"
                 : "=r"(r0), "=r"(r1) : "r"(a));
}
__device__ __forceinline__ void hmma(float d[4], unsigned a0, unsigned a1, unsigned a2, unsigned a3,
                                     unsigned b0, unsigned b1) {
    asm volatile("mma.sync.aligned.m16n8k16.row.col.f32.f16.f16.f32 "
                 "{%0,%1,%2,%3},{%4,%5,%6,%7},{%8,%9},{%0,%1,%2,%3};"
                 : "+f"(d[0]), "+f"(d[1]), "+f"(d[2]), "+f"(d[3])
                 : "r"(a0), "r"(a1), "r"(a2), "r"(a3), "r"(b0), "r"(b1));
}
__device__ __forceinline__ float sig_(float x) { return 1.0f / (1.0f + __expf(-x)); }

// ---------------- single merged prep kernel ---------------------------------
// permuted col index pn -> (gate, unit):
//   nn=pn&15; half=nn>>3; a=(nn&7)>>1; s=nn&1; gate=half*2+s; unit=(pn>>4)*4+a
__global__ void prep_all(const float* __restrict__ Wih, const float* __restrict__ Whh,
                         const float* __restrict__ h0,  const float* __restrict__ Wfc) {
    int i = blockIdx.x * blockDim.x + threadIdx.x;
    int stride = gridDim.x * blockDim.x;
    const int totalG = 2 * NCTA * 32 * HID;
    for (int e = i; e < totalG; e += stride) {
        int k = e & (HID - 1);
        int pn = (e >> 10) & 31;
        int cta = (e >> 15) & (NCTA - 1);
        int l = e >> 22;
        int nn = pn & 15, half = nn >> 3, a = (nn & 7) >> 1, s = nn & 1;
        int gate = half * 2 + s, unit = (pn >> 4) * 4 + a;
        size_t src = (size_t)l * 4 * HID * HID + (size_t)(gate * HID + cta * 8 + unit) * HID + k;
        g_Whh_p[e] = __float2half_rn(Whh[src]);
        g_Wst[(size_t)((l * NCTA + cta) * 40 + pn) * HID + k] = __float2half_rn(Wih[src]);
    }
    const int totalF = 2 * NCTA * 8 * HID;
    for (int e = i; e < totalF; e += stride) {
        int k = e & (HID - 1);
        int u = (e >> 10) & 7;
        int cta = (e >> 13) & (NCTA - 1);
        int l = e >> 20;
        g_Wst[(size_t)((l * NCTA + cta) * 40 + 32 + u) * HID + k] =
            __float2half_rn(Wfc[(size_t)(cta * 8 + u) * HID + k]);
    }
    for (int e = i; e < BATCH * HID; e += stride) g_x0[e] = __float2half_rn(h0[e]);
    for (int e = i; e < 4 * BATCH * HID; e += stride) g_hbuf[e] = __float2half_rn(0.0f);
    if (i == 0) g_bar = 0;
}

// ---------------- split grid barrier ---------------------------------------
__device__ __forceinline__ void gbar_arrive() {
    __syncthreads();
    if (threadIdx.x == 0)
        asm volatile("red.release.gpu.add.u32 [%0], %1;" :: "l"(&g_bar), "r"(1u) : "memory");
}
__device__ __forceinline__ void gbar_wait(unsigned target) {
    if (threadIdx.x == 0) {
        unsigned v;
        do {
            asm volatile("ld.acquire.gpu.u32 %0, [%1];" : "=r"(v) : "l"(&g_bar));
        } while (v < target);
    }
    __syncthreads();
}

// ---------------- staging ---------------------------------------------------
__device__ __forceinline__ void stage_act(__half* dst, const __half* src, int k0, int tid) {
    #pragma unroll
    for (int i = 0; i < 4; i++) {
        int e = tid + i * THREADS;          // 1024 ops: 64 rows x 16 segs
        int r = e >> 4, sg = e & 15;
        cp16cg(dst + r * SA + sg * 8, src + r * HID + k0 + sg * 8);
    }
}
__device__ __forceinline__ void stage_w40(__half* dst, const __half* src, int k0, int tid) {
    #pragma unroll
    for (int i = 0; i < 3; i++) {
        int e = tid + i * THREADS;          // 640 ops: 40 rows x 16 segs
        if (e < 640) {
            int r = e >> 4, sg = e & 15;
            cp16(dst + r * SW + sg * 8, src + r * HID + k0 + sg * 8);
        }
    }
}
__device__ __forceinline__ void stage_w32(__half* dst, const __half* src, int k0, int tid) {
    #pragma unroll
    for (int i = 0; i < 2; i++) {
        int e = tid + i * THREADS;          // 512 ops: 32 rows x 16 segs
        int r = e >> 4, sg = e & 15;
        cp16(dst + r * SW + sg * 8, src + r * HID + k0 + sg * 8);
    }
}

// ---------------- main persistent kernel ------------------------------------
__global__ __launch_bounds__(THREADS, 1) void lstm_persist(
    const float* __restrict__ bih, const float* __restrict__ bhh,
    const float* __restrict__ bfc, float* __restrict__ out)
{
    extern __shared__ __align__(16) unsigned char smem_raw[];
    __half* actS  = (__half*)smem_raw;            // [8 slots][64][SA] persistent acts
    __half* wringS = actS + 8 * 64 * SA;          // [4][40][SW] weight ring (+ epi scratch)
    float*  cS    = (float*)(wringS + 4 * 40 * SW);// [2][64][8]
    float*  biasS = cS + 2 * 64 * 8;              // [2][32]
    float*  fcbS  = biasS + 64;                   // [8]
    float*  wscr  = (float*)wringS;               // epilogue reduce scratch

    const int tid  = threadIdx.x;
    const int warp = tid >> 5;
    const int lane = tid & 31;
    const int m2   = warp & 1;     // 32-row M half
    const int ks   = warp >> 1;    // k16 split (k16 in {ks, ks+4})
    const int cta  = blockIdx.x;
    const int j0   = cta * 8;

    const unsigned ABUF = 64 * SA * 2;   // act slot stride (bytes)
    const unsigned WBUF = 40 * SW * 2;   // W slot stride (bytes)
    const int ABUFH = 64 * SA;           // act slot stride (halfs)
    const int WBUFH = 40 * SW;

    // ---- biases / cell state ----
    if (tid < 64) {
        int l = tid >> 5, pn = tid & 31;
        int nn = pn & 15, half = nn >> 3, a = (nn & 7) >> 1, s = nn & 1;
        int gate = half * 2 + s, unit = (pn >> 4) * 4 + a;
        int row = gate * HID + j0 + unit;
        biasS[l * 32 + pn] = bih[l * 4 * HID + row] + bhh[l * 4 * HID + row];
    }
    if (tid < 8) fcbS[tid] = bfc[j0 + tid];
    #pragma unroll
    for (int i = 0; i < 4; i++) cS[tid + i * THREADS] = 0.0f;
    __syncthreads();

    // per-lane fragment base addresses (slot delta added at use)
    const unsigned xbA0[2] = {
        sptr(actS) + ((m2 * 32 + 0  + (lane & 15)) * SA + (lane >> 4) * 8) * 2,
        sptr(actS) + ((m2 * 32 + 16 + (lane & 15)) * SA + (lane >> 4) * 8) * 2 };
    const unsigned wbB0[2] = {
        sptr(wringS) + ((0  + (lane & 15)) * SW + (lane >> 4) * 8) * 2,
        sptr(wringS) + ((16 + (lane & 15)) * SW + (lane >> 4) * 8) * 2 };
    const unsigned fcB0 =
        sptr(wringS) + ((32 + (lane & 7)) * SW + ((lane >> 3) & 1) * 8) * 2;

    unsigned barTarget = 0;
    const int r = lane >> 2, a4 = lane & 3;

    // W ring slot state (continuous across phases)
    int w_stage = 0, w_cons = 0;

    for (int t = 0; t < TSTEPS; t++) {
        const int p = t & 1, q = p ^ 1;
        #pragma unroll 1
        for (int l = 0; l < 2; l++) {
            const __half* xsrc = (l == 0)
                ? ((t == 0) ? g_x0 : g_hbuf + (2 + q) * BATCH * HID)
                : g_hbuf + (0 + p) * BATCH * HID;
            __half* hdst = g_hbuf + (l * 2 + p) * BATCH * HID;
            const __half* wsrc  = g_Wst   + (size_t)(l * NCTA + cta) * 40 * HID;
            const __half* whsrc = g_Whh_p + (size_t)(l * NCTA + cta) * 32 * HID;
            const bool fc_phase = (l == 0) && (t > 0);

            float acc[2][4][4];
            #pragma unroll
            for (int a = 0; a < 2; a++)
                #pragma unroll
                for (int b = 0; b < 4; b++)
                    #pragma unroll
                    for (int c2 = 0; c2 < 4; c2++) acc[a][b][c2] = 0.0f;
            float fca[2][4] = {{0,0,0,0},{0,0,0,0}};

            // ===== part A: h_rec @ Whh. h is ALREADY in the 8 act slots
            //       (written as x by the previous phase's part B).
            //       t==0: h == 0 for both layers -> part A skipped. =====
            if (t > 0) {
                #pragma unroll
                for (int i = 0; i < 3; i++) {
                    stage_w32(wringS + w_stage * WBUFH, whsrc, i * KC, tid); cp_commit();
                    w_stage = NX4(w_stage);
                }
                #pragma unroll 1
                for (int kc = 0; kc < NKC; kc++) {
                    cp_wait<2>();
                    __syncthreads();
                    if (kc + 3 < NKC) {
                        stage_w32(wringS + w_stage * WBUFH, whsrc, (kc + 3) * KC, tid);
                        w_stage = NX4(w_stage);
                    }
                    cp_commit();
                    const unsigned xd = (unsigned)kc * ABUF;
                    const unsigned wd = (unsigned)w_cons * WBUF;
                    w_cons = NX4(w_cons);
                    #pragma unroll
                    for (int j = 0; j < 2; j++) {
                        const int k16 = ks + j * 4;
                        unsigned a0[2][4], b0[2][4];
                        #pragma unroll
                        for (int mf = 0; mf < 2; mf++)
                            ldsm_x4(a0[mf][0], a0[mf][1], a0[mf][2], a0[mf][3],
                                    xbA0[mf] + xd + k16 * 32);
                        #pragma unroll
                        for (int cg = 0; cg < 2; cg++)
                            ldsm_x4(b0[cg][0], b0[cg][1], b0[cg][2], b0[cg][3],
                                    wbB0[cg] + wd + k16 * 32);
                        #pragma unroll
                        for (int mf = 0; mf < 2; mf++)
                            #pragma unroll
                            for (int cg = 0; cg < 2; cg++) {
                                hmma(acc[mf][cg * 2 + 0], a0[mf][0], a0[mf][1], a0[mf][2], a0[mf][3],
                                     b0[cg][0], b0[cg][2]);
                                hmma(acc[mf][cg * 2 + 1], a0[mf][0], a0[mf][1], a0[mf][2], a0[mf][3],
                                     b0[cg][1], b0[cg][3]);
                            }
                    }
                }
            }

            // ===== barrier wait (mostly satisfied already) =====
            gbar_wait(barTarget);

            // ===== part B: x @ [Wih | Wfc]; x lands in slots 0..7 and
            //       becomes next phase's part-A h. =====
            #pragma unroll
            for (int i = 0; i < 3; i++) {
                stage_act(actS + i * ABUFH, xsrc, i * KC, tid);
                stage_w40(wringS + w_stage * WBUFH, wsrc, i * KC, tid);
                cp_commit();
                w_stage = NX4(w_stage);
            }
            #pragma unroll 1
            for (int kc = 0; kc < NKC; kc++) {
                cp_wait<2>();
                __syncthreads();
                if (kc + 3 < NKC) {
                    stage_act(actS + (kc + 3) * ABUFH, xsrc, (kc + 3) * KC, tid);
                    stage_w40(wringS + w_stage * WBUFH, wsrc, (kc + 3) * KC, tid);
                    w_stage = NX4(w_stage);
                }
                cp_commit();
                const unsigned xd = (unsigned)kc * ABUF;
                const unsigned wd = (unsigned)w_cons * WBUF;
                w_cons = NX4(w_cons);
                #pragma unroll
                for (int j = 0; j < 2; j++) {
                    const int k16 = ks + j * 4;
                    unsigned a0[2][4], b0[2][4];
                    #pragma unroll
                    for (int mf = 0; mf < 2; mf++)
                        ldsm_x4(a0[mf][0], a0[mf][1], a0[mf][2], a0[mf][3],
                                xbA0[mf] + xd + k16 * 32);
                    #pragma unroll
                    for (int cg = 0; cg < 2; cg++)
                        ldsm_x4(b0[cg][0], b0[cg][1], b0[cg][2], b0[cg][3],
                                wbB0[cg] + wd + k16 * 32);
                    #pragma unroll
                    for (int mf = 0; mf < 2; mf++)
                        #pragma unroll
                        for (int cg = 0; cg < 2; cg++) {
                            hmma(acc[mf][cg * 2 + 0], a0[mf][0], a0[mf][1], a0[mf][2], a0[mf][3],
                                 b0[cg][0], b0[cg][2]);
                            hmma(acc[mf][cg * 2 + 1], a0[mf][0], a0[mf][1], a0[mf][2], a0[mf][3],
                                 b0[cg][1], b0[cg][3]);
                        }
                    if (fc_phase) {
                        unsigned f0, f1;
                        ldsm_x2(f0, f1, fcB0 + wd + k16 * 32);
                        #pragma unroll
                        for (int mf = 0; mf < 2; mf++)
                            hmma(fca[mf], a0[mf][0], a0[mf][1], a0[mf][2], a0[mf][3], f0, f1);
                    }
                }
            }

            // ===== epilogue (R11 form: compile-time register indexing) ======
            __syncthreads();           // all W-ring reads done before scratch reuse
            if (ks > 0) {
                float* sp = wscr + (((ks - 1) * 2 + m2) * 32 + lane) * 40;
                #pragma unroll
                for (int mf = 0; mf < 2; mf++)
                    #pragma unroll
                    for (int nf = 0; nf < 4; nf++)
                        #pragma unroll
                        for (int c2 = 0; c2 < 4; c2++)
                            sp[(mf * 4 + nf) * 4 + c2] = acc[mf][nf][c2];
                #pragma unroll
                for (int mf = 0; mf < 2; mf++)
                    #pragma unroll
                    for (int c2 = 0; c2 < 4; c2++)
                        sp[32 + mf * 4 + c2] = fca[mf][c2];
            }
            __syncthreads();
            if (ks == 0) {
                #pragma unroll
                for (int sl = 0; sl < 3; sl++) {
                    const float* sp = wscr + ((sl * 2 + m2) * 32 + lane) * 40;
                    #pragma unroll
                    for (int mf = 0; mf < 2; mf++)
                        #pragma unroll
                        for (int nf = 0; nf < 4; nf++)
                            #pragma unroll
                            for (int c2 = 0; c2 < 4; c2++)
                                acc[mf][nf][c2] += sp[(mf * 4 + nf) * 4 + c2];
                    #pragma unroll
                    for (int mf = 0; mf < 2; mf++)
                        #pragma unroll
                        for (int c2 = 0; c2 < 4; c2++)
                            fca[mf][c2] += sp[32 + mf * 4 + c2];
                }

                float* crow = cS + l * 64 * 8;
                float* op = out + (size_t)(t - 1) * BATCH * HID;
                #pragma unroll
                for (int mf = 0; mf < 2; mf++) {
                    #pragma unroll
                    for (int rp = 0; rp < 2; rp++) {
                        const int b = m2 * 32 + mf * 16 + rp * 8 + r;
                        const int k = rp * 2;
                        #pragma unroll
                        for (int ug = 0; ug < 2; ug++) {
                            const int u = ug * 4 + a4;
                            float iv = acc[mf][ug * 2 + 0][k + 0] + biasS[l * 32 + ug * 16 + a4 * 2 + 0];
                            float fv = acc[mf][ug * 2 + 0][k + 1] + biasS[l * 32 + ug * 16 + a4 * 2 + 1];
                            float gv = acc[mf][ug * 2 + 1][k + 0] + biasS[l * 32 + ug * 16 + 8 + a4 * 2 + 0];
                            float ov = acc[mf][ug * 2 + 1][k + 1] + biasS[l * 32 + ug * 16 + 8 + a4 * 2 + 1];
                            float cn = sig_(fv) * crow[b * 8 + u] + sig_(iv) * tanhf(gv);
                            crow[b * 8 + u] = cn;
                            hdst[b * HID + j0 + u] = __float2half_rn(sig_(ov) * tanhf(cn));
                        }
                        if (fc_phase) {
                            op[b * HID + j0 + a4 * 2 + 0] = fca[mf][k + 0] + fcbS[a4 * 2 + 0];
                            op[b * HID + j0 + a4 * 2 + 1] = fca[mf][k + 1] + fcbS[a4 * 2 + 1];
                        }
                    }
                }
            }
            gbar_arrive();
            barTarget += NCTA;
        }
    }

    // ===== final FC for t = T-1 (x = h1 written at t=127, parity 1) =====
    {
        gbar_wait(barTarget);
        const __half* xsrc = g_hbuf + (2 + 1) * BATCH * HID;
        const __half* wsrc = g_Wst + (size_t)(0 * NCTA + cta) * 40 * HID;
        float fca[2][4] = {{0,0,0,0},{0,0,0,0}};
        #pragma unroll
        for (int i = 0; i < 3; i++) {
            stage_act(actS + i * ABUFH, xsrc, i * KC, tid);
            stage_w40(wringS + w_stage * WBUFH, wsrc, i * KC, tid);
            cp_commit();
            w_stage = NX4(w_stage);
        }
        #pragma unroll 1
        for (int kc = 0; kc < NKC; kc++) {
            cp_wait<2>();
            __syncthreads();
            if (kc + 3 < NKC) {
                stage_act(actS + (kc + 3) * ABUFH, xsrc, (kc + 3) * KC, tid);
                stage_w40(wringS + w_stage * WBUFH, wsrc, (kc + 3) * KC, tid);
                w_stage = NX4(w_stage);
            }
            cp_commit();
            const unsigned xd = (unsigned)kc * ABUF;
            const unsigned wd = (unsigned)w_cons * WBUF;
            w_cons = NX4(w_cons);
            #pragma unroll
            for (int j = 0; j < 2; j++) {
                const int k16 = ks + j * 4;
                unsigned f0, f1;
                ldsm_x2(f0, f1, fcB0 + wd + k16 * 32);
                #pragma unroll
                for (int mf = 0; mf < 2; mf++) {
                    unsigned a0, a1, a2, a3;
                    ldsm_x4(a0, a1, a2, a3, xbA0[mf] + xd + k16 * 32);
                    hmma(fca[mf], a0, a1, a2, a3, f0, f1);
                }
            }
        }
        __syncthreads();
        if (ks > 0) {
            float* sp = wscr + (((ks - 1) * 2 + m2) * 32 + lane) * 40;
            #pragma unroll
            for (int mf = 0; mf < 2; mf++)
                #pragma unroll
                for (int c2 = 0; c2 < 4; c2++)
                    sp[32 + mf * 4 + c2] = fca[mf][c2];
        }
        __syncthreads();
        if (ks == 0) {
            #pragma unroll
            for (int sl = 0; sl < 3; sl++) {
                const float* sp = wscr + ((sl * 2 + m2) * 32 + lane) * 40;
                #pragma unroll
                for (int mf = 0; mf < 2; mf++)
                    #pragma unroll
                    for (int c2 = 0; c2 < 4; c2++)
                        fca[mf][c2] += sp[32 + mf * 4 + c2];
            }
            float* op = out + (size_t)(TSTEPS - 1) * BATCH * HID;
            #pragma unroll
            for (int mf = 0; mf < 2; mf++)
                #pragma unroll
                for (int rp = 0; rp < 2; rp++) {
                    const int b = m2 * 32 + mf * 16 + rp * 8 + r;
                    const int k = rp * 2;
                    op[b * HID + j0 + a4 * 2 + 0] = fca[mf][k + 0] + fcbS[a4 * 2 + 0];
                    op[b * HID + j0 + a4 * 2 + 1] = fca[mf][k + 1] + fcbS[a4 * 2 + 1];
                }
        }
    }
}

// ---------------- host launch -----------------------------------------------
extern "C" void kernel_launch(void* const* d_in, const int* in_sizes, int n_in,
                              void* d_out, int out_size) {
    const float* h0  = (const float*)d_in[0];
    const float* Wih = (const float*)d_in[1];
    const float* Whh = (const float*)d_in[2];
    const float* bih = (const float*)d_in[3];
    const float* bhh = (const float*)d_in[4];
    const float* Wfc = (const float*)d_in[5];
    const float* bfc = (const float*)d_in[6];
    float* out = (float*)d_out;

    const int smem = (8 * 64 * SA + 4 * 40 * SW) * 2
                   + (2 * 64 * 8 + 64 + 8) * 4;
    cudaFuncSetAttribute(lstm_persist, cudaFuncAttributeMaxDynamicSharedMemorySize, smem);

    prep_all<<<2048, 256>>>(Wih, Whh, h0, Wfc);
    lstm_persist<<<NCTA, THREADS, smem>>>(bih, bhh, bfc, out);
}

// round 16
// speedup vs baseline: 1.5129x; 1.5129x over previous
#include <cuda_runtime.h>
#include <cuda_fp16.h>
#include <math.h>

// Persistent-kernel LSTM decoder. B=64, H=1024, L=2, T=128.
// 128 CTAs (1/SM), 256 threads (8 warps). warp=(ks,m2) 32x32 tile over
// k16s {ks,ks+4}; release-atomic grid barrier; R11/R14 epilogue
// (compile-time register indexing). R14 base: activation identity (part-A h
// == previous part-B x in 8 persistent SMEM slots); Whh streamed; t==0
// part A skipped. Depth-2 prefetch ONLY (depth-3 regressed twice: deeper
// in-flight load queues widen cross-CTA spread, amplified by the barrier).
// R16: CONTINUOUS WEIGHT STREAM -- weights are barrier-free, so part A's
// Whh chunks {0,1} are staged in the previous part B's idle slots (kc=6,7)
// and part B's Wih/FC chunks {0,1} in part A's idle slots. No cold W fill
// at any part boundary; only the post-barrier x-act stage remains exposed.
// Epilogue scratch moved to a dedicated buffer (W ring now always live).

#define BATCH   64
#define HID     1024
#define TSTEPS  128
#define NCTA    128
#define THREADS 256
#define SA      136    // act slot row stride (halfs)
#define SW      136    // streamed weight row stride (halfs)
#define KC      128    // K chunk
#define NKC     8      // chunks per matrix
#define NX3(s)  (((s) + 1 == 3) ? 0 : (s) + 1)

// ---------------- device globals (pre-permuted fp16 weights + state) -------
__device__ __half g_Wst[2 * NCTA * 40 * HID];     // [l][cta][40 rows][k]: 32 Wih + 8 FC
__device__ __half g_Whh_p[2 * NCTA * 32 * HID];   // [l][cta][32][k] recurrent
__device__ __half g_hbuf[4 * BATCH * HID];        // [l*2+parity][b][h]
__device__ __half g_x0[BATCH * HID];
__device__ unsigned g_bar;

// ---------------- small asm helpers ---------------------------------------
__device__ __forceinline__ unsigned sptr(const void* p) {
    return (unsigned)__cvta_generic_to_shared(p);
}
__device__ __forceinline__ void cp16(void* s, const void* g) {      // weights (.ca)
    asm volatile("cp.async.ca.shared.global [%0], [%1], 16;" :: "r"(sptr(s)), "l"(g));
}
__device__ __forceinline__ void cp16cg(void* s, const void* g) {    // acts (.cg)
    asm volatile("cp.async.cg.shared.global [%0], [%1], 16;" :: "r"(sptr(s)), "l"(g));
}
__device__ __forceinline__ void cp_commit() {
    asm volatile("cp.async.commit_group;");
}
template<int N> __device__ __forceinline__ void cp_wait() {
    asm volatile("cp.async.wait_group %0;" :: "n"(N));
}
__device__ __forceinline__ void ldsm_x4(unsigned &r0, unsigned &r1, unsigned &r2, unsigned &r3, unsigned a) {
    asm volatile("ldmatrix.sync.aligned.m8n8.x4.shared.b16 {%0,%1,%2,%3}, [%4];"
                 : "=r"(r0), "=r"(r1), "=r"(r2), "=r"(r3) : "r"(a));
}
__device__ __forceinline__ void ldsm_x2(unsigned &r0, unsigned &r1, unsigned a) {
    asm volatile("ldmatrix.sync.aligned.m8n8.x2.shared.b16 {%0,%1}, [%2];"
                 : "=r"(r0), "=r"(r1) : "r"(a));
}
__device__ __forceinline__ void hmma(float d[4], unsigned a0, unsigned a1, unsigned a2, unsigned a3,
                                     unsigned b0, unsigned b1) {
    asm volatile("mma.sync.aligned.m16n8k16.row.col.f32.f16.f16.f32 "
                 "{%0,%1,%2,%3},{%4,%5,%6,%7},{%8,%9},{%0,%1,%2,%3};"
                 : "+f"(d[0]), "+f"(d[1]), "+f"(d[2]), "+f"(d[3])
                 : "r"(a0), "r"(a1), "r"(a2), "r"(a3), "r"(b0), "r"(b1));
}
__device__ __forceinline__ float sig_(float x) { return 1.0f / (1.0f + __expf(-x)); }

// ---------------- single merged prep kernel ---------------------------------
// permuted col index pn -> (gate, unit):
//   nn=pn&15; half=nn>>3; a=(nn&7)>>1; s=nn&1; gate=half*2+s; unit=(pn>>4)*4+a
__global__ void prep_all(const float* __restrict__ Wih, const float* __restrict__ Whh,
                         const float* __restrict__ h0,  const float* __restrict__ Wfc) {
    int i = blockIdx.x * blockDim.x + threadIdx.x;
    int stride = gridDim.x * blockDim.x;
    const int totalG = 2 * NCTA * 32 * HID;
    for (int e = i; e < totalG; e += stride) {
        int k = e & (HID - 1);
        int pn = (e >> 10) & 31;
        int cta = (e >> 15) & (NCTA - 1);
        int l = e >> 22;
        int nn = pn & 15, half = nn >> 3, a = (nn & 7) >> 1, s = nn & 1;
        int gate = half * 2 + s, unit = (pn >> 4) * 4 + a;
        size_t src = (size_t)l * 4 * HID * HID + (size_t)(gate * HID + cta * 8 + unit) * HID + k;
        g_Whh_p[e] = __float2half_rn(Whh[src]);
        g_Wst[(size_t)((l * NCTA + cta) * 40 + pn) * HID + k] = __float2half_rn(Wih[src]);
    }
    const int totalF = 2 * NCTA * 8 * HID;
    for (int e = i; e < totalF; e += stride) {
        int k = e & (HID - 1);
        int u = (e >> 10) & 7;
        int cta = (e >> 13) & (NCTA - 1);
        int l = e >> 20;
        g_Wst[(size_t)((l * NCTA + cta) * 40 + 32 + u) * HID + k] =
            __float2half_rn(Wfc[(size_t)(cta * 8 + u) * HID + k]);
    }
    for (int e = i; e < BATCH * HID; e += stride) g_x0[e] = __float2half_rn(h0[e]);
    for (int e = i; e < 4 * BATCH * HID; e += stride) g_hbuf[e] = __float2half_rn(0.0f);
    if (i == 0) g_bar = 0;
}

// ---------------- split grid barrier ---------------------------------------
__device__ __forceinline__ void gbar_arrive() {
    __syncthreads();
    if (threadIdx.x == 0)
        asm volatile("red.release.gpu.add.u32 [%0], %1;" :: "l"(&g_bar), "r"(1u) : "memory");
}
__device__ __forceinline__ void gbar_wait(unsigned target) {
    if (threadIdx.x == 0) {
        unsigned v;
        do {
            asm volatile("ld.acquire.gpu.u32 %0, [%1];" : "=r"(v) : "l"(&g_bar));
        } while (v < target);
    }
    __syncthreads();
}

// ---------------- staging ---------------------------------------------------
__device__ __forceinline__ void stage_act(__half* dst, const __half* src, int k0, int tid) {
    #pragma unroll
    for (int i = 0; i < 4; i++) {
        int e = tid + i * THREADS;          // 1024 ops: 64 rows x 16 segs
        int r = e >> 4, sg = e & 15;
        cp16cg(dst + r * SA + sg * 8, src + r * HID + k0 + sg * 8);
    }
}
__device__ __forceinline__ void stage_w40(__half* dst, const __half* src, int k0, int tid) {
    #pragma unroll
    for (int i = 0; i < 3; i++) {
        int e = tid + i * THREADS;          // 640 ops: 40 rows x 16 segs
        if (e < 640) {
            int r = e >> 4, sg = e & 15;
            cp16(dst + r * SW + sg * 8, src + r * HID + k0 + sg * 8);
        }
    }
}
__device__ __forceinline__ void stage_w32(__half* dst, const __half* src, int k0, int tid) {
    #pragma unroll
    for (int i = 0; i < 2; i++) {
        int e = tid + i * THREADS;          // 512 ops: 32 rows x 16 segs
        int r = e >> 4, sg = e & 15;
        cp16(dst + r * SW + sg * 8, src + r * HID + k0 + sg * 8);
    }
}

// ---------------- main persistent kernel ------------------------------------
__global__ __launch_bounds__(THREADS, 1) void lstm_persist(
    const float* __restrict__ bih, const float* __restrict__ bhh,
    const float* __restrict__ bfc, float* __restrict__ out)
{
    extern __shared__ __align__(16) unsigned char smem_raw[];
    __half* actS  = (__half*)smem_raw;            // [8 slots][64][SA] persistent acts
    __half* wringS = actS + 8 * 64 * SA;          // [3][40][SW] continuous weight ring
    float*  scrS  = (float*)(wringS + 3 * 40 * SW);// [6*32*40] epilogue reduce scratch
    float*  cS    = scrS + 6 * 32 * 40;           // [2][64][8]
    float*  biasS = cS + 2 * 64 * 8;              // [2][32]
    float*  fcbS  = biasS + 64;                   // [8]

    const int tid  = threadIdx.x;
    const int warp = tid >> 5;
    const int lane = tid & 31;
    const int m2   = warp & 1;     // 32-row M half
    const int ks   = warp >> 1;    // k16 split (k16 in {ks, ks+4})
    const int cta  = blockIdx.x;
    const int j0   = cta * 8;

    const unsigned ABUF = 64 * SA * 2;   // act slot stride (bytes)
    const unsigned WBUF = 40 * SW * 2;   // W slot stride (bytes)
    const int ABUFH = 64 * SA;           // act slot stride (halfs)
    const int WBUFH = 40 * SW;

    // ---- biases / cell state ----
    if (tid < 64) {
        int l = tid >> 5, pn = tid & 31;
        int nn = pn & 15, half = nn >> 3, a = (nn & 7) >> 1, s = nn & 1;
        int gate = half * 2 + s, unit = (pn >> 4) * 4 + a;
        int row = gate * HID + j0 + unit;
        biasS[l * 32 + pn] = bih[l * 4 * HID + row] + bhh[l * 4 * HID + row];
    }
    if (tid < 8) fcbS[tid] = bfc[j0 + tid];
    #pragma unroll
    for (int i = 0; i < 4; i++) cS[tid + i * THREADS] = 0.0f;
    __syncthreads();

    // per-lane fragment base addresses (slot delta added at use)
    const unsigned xbA0[2] = {
        sptr(actS) + ((m2 * 32 + 0  + (lane & 15)) * SA + (lane >> 4) * 8) * 2,
        sptr(actS) + ((m2 * 32 + 16 + (lane & 15)) * SA + (lane >> 4) * 8) * 2 };
    const unsigned wbB0[2] = {
        sptr(wringS) + ((0  + (lane & 15)) * SW + (lane >> 4) * 8) * 2,
        sptr(wringS) + ((16 + (lane & 15)) * SW + (lane >> 4) * 8) * 2 };
    const unsigned fcB0 =
        sptr(wringS) + ((32 + (lane & 7)) * SW + ((lane >> 3) & 1) * 8) * 2;

    unsigned barTarget = 0;
    const int r = lane >> 2, a4 = lane & 3;

    // W ring slot state (continuous across phases and parts)
    int w_stage = 0, w_cons = 0;

    for (int t = 0; t < TSTEPS; t++) {
        const int p = t & 1, q = p ^ 1;
        #pragma unroll 1
        for (int l = 0; l < 2; l++) {
            const __half* xsrc = (l == 0)
                ? ((t == 0) ? g_x0 : g_hbuf + (2 + q) * BATCH * HID)
                : g_hbuf + (0 + p) * BATCH * HID;
            __half* hdst = g_hbuf + (l * 2 + p) * BATCH * HID;
            const __half* wsrc  = g_Wst   + (size_t)(l * NCTA + cta) * 40 * HID;
            const __half* whsrc = g_Whh_p + (size_t)(l * NCTA + cta) * 32 * HID;
            // next phase's Whh (layer l^1); legal always (static weights)
            const __half* nwhsrc = g_Whh_p + (size_t)((l ^ 1) * NCTA + cta) * 32 * HID;
            const bool fc_phase = (l == 0) && (t > 0);
            // next phase runs part A unless next phase is (0,1) or we're last
            const bool stage_nwh = !(t == 0 && l == 0) && !(t == TSTEPS - 1 && l == 1);

            float acc[2][4][4];
            #pragma unroll
            for (int a = 0; a < 2; a++)
                #pragma unroll
                for (int b = 0; b < 4; b++)
                    #pragma unroll
                    for (int c2 = 0; c2 < 4; c2++) acc[a][b][c2] = 0.0f;
            float fca[2][4] = {{0,0,0,0},{0,0,0,0}};

            // ===== part A: h_rec @ Whh. h is ALREADY in the 8 act slots;
            //       Whh chunks {0,1} already staged by previous part B.
            //       kc==6/7 idle stage slots carry part B's Wih/FC {0,1}.
            //       t==0: h == 0 -> part A skipped. =====
            if (t > 0) {
                #pragma unroll 1
                for (int kc = 0; kc < NKC; kc++) {
                    cp_wait<1>();
                    __syncthreads();
                    if (kc + 2 < NKC) {
                        stage_w32(wringS + w_stage * WBUFH, whsrc, (kc + 2) * KC, tid);
                        w_stage = NX3(w_stage);
                    } else {
                        stage_w40(wringS + w_stage * WBUFH, wsrc, (kc - 6) * KC, tid);
                        w_stage = NX3(w_stage);
                    }
                    cp_commit();
                    const unsigned xd = (unsigned)kc * ABUF;
                    const unsigned wd = (unsigned)w_cons * WBUF;
                    w_cons = NX3(w_cons);
                    #pragma unroll
                    for (int j = 0; j < 2; j++) {
                        const int k16 = ks + j * 4;
                        unsigned a0[2][4], b0[2][4];
                        #pragma unroll
                        for (int mf = 0; mf < 2; mf++)
                            ldsm_x4(a0[mf][0], a0[mf][1], a0[mf][2], a0[mf][3],
                                    xbA0[mf] + xd + k16 * 32);
                        #pragma unroll
                        for (int cg = 0; cg < 2; cg++)
                            ldsm_x4(b0[cg][0], b0[cg][1], b0[cg][2], b0[cg][3],
                                    wbB0[cg] + wd + k16 * 32);
                        #pragma unroll
                        for (int mf = 0; mf < 2; mf++)
                            #pragma unroll
                            for (int cg = 0; cg < 2; cg++) {
                                hmma(acc[mf][cg * 2 + 0], a0[mf][0], a0[mf][1], a0[mf][2], a0[mf][3],
                                     b0[cg][0], b0[cg][2]);
                                hmma(acc[mf][cg * 2 + 1], a0[mf][0], a0[mf][1], a0[mf][2], a0[mf][3],
                                     b0[cg][1], b0[cg][3]);
                            }
                    }
                }
            }

            // ===== barrier wait (mostly satisfied already) =====
            gbar_wait(barTarget);

            // ===== part B prologue: acts {0,1} (W already in flight when
            //       part A ran; at t==0 stage W here too). =====
            if (t > 0) {
                #pragma unroll
                for (int i = 0; i < 2; i++) {
                    stage_act(actS + i * ABUFH, xsrc, i * KC, tid);
                    cp_commit();
                }
            } else {
                #pragma unroll
                for (int i = 0; i < 2; i++) {
                    stage_act(actS + i * ABUFH, xsrc, i * KC, tid);
                    stage_w40(wringS + w_stage * WBUFH, wsrc, i * KC, tid);
                    w_stage = NX3(w_stage);
                    cp_commit();
                }
            }

            // ===== part B: x @ [Wih | Wfc]; x lands in slots 0..7 and
            //       becomes next phase's part-A h. kc==6/7 idle stage slots
            //       carry the NEXT phase's Whh {0,1}. =====
            #pragma unroll 1
            for (int kc = 0; kc < NKC; kc++) {
                cp_wait<1>();
                __syncthreads();
                if (kc + 2 < NKC) {
                    stage_act(actS + (kc + 2) * ABUFH, xsrc, (kc + 2) * KC, tid);
                    stage_w40(wringS + w_stage * WBUFH, wsrc, (kc + 2) * KC, tid);
                    w_stage = NX3(w_stage);
                } else if (stage_nwh) {
                    stage_w32(wringS + w_stage * WBUFH, nwhsrc, (kc - 6) * KC, tid);
                    w_stage = NX3(w_stage);
                }
                cp_commit();
                const unsigned xd = (unsigned)kc * ABUF;
                const unsigned wd = (unsigned)w_cons * WBUF;
                w_cons = NX3(w_cons);
                #pragma unroll
                for (int j = 0; j < 2; j++) {
                    const int k16 = ks + j * 4;
                    unsigned a0[2][4], b0[2][4];
                    #pragma unroll
                    for (int mf = 0; mf < 2; mf++)
                        ldsm_x4(a0[mf][0], a0[mf][1], a0[mf][2], a0[mf][3],
                                xbA0[mf] + xd + k16 * 32);
                    #pragma unroll
                    for (int cg = 0; cg < 2; cg++)
                        ldsm_x4(b0[cg][0], b0[cg][1], b0[cg][2], b0[cg][3],
                                wbB0[cg] + wd + k16 * 32);
                    #pragma unroll
                    for (int mf = 0; mf < 2; mf++)
                        #pragma unroll
                        for (int cg = 0; cg < 2; cg++) {
                            hmma(acc[mf][cg * 2 + 0], a0[mf][0], a0[mf][1], a0[mf][2], a0[mf][3],
                                 b0[cg][0], b0[cg][2]);
                            hmma(acc[mf][cg * 2 + 1], a0[mf][0], a0[mf][1], a0[mf][2], a0[mf][3],
                                 b0[cg][1], b0[cg][3]);
                        }
                    if (fc_phase) {
                        unsigned f0, f1;
                        ldsm_x2(f0, f1, fcB0 + wd + k16 * 32);
                        #pragma unroll
                        for (int mf = 0; mf < 2; mf++)
                            hmma(fca[mf], a0[mf][0], a0[mf][1], a0[mf][2], a0[mf][3], f0, f1);
                    }
                }
            }

            // ===== epilogue (R11 form; dedicated scratch) ===================
            __syncthreads();
            if (ks > 0) {
                float* sp = scrS + (((ks - 1) * 2 + m2) * 32 + lane) * 40;
                #pragma unroll
                for (int mf = 0; mf < 2; mf++)
                    #pragma unroll
                    for (int nf = 0; nf < 4; nf++)
                        #pragma unroll
                        for (int c2 = 0; c2 < 4; c2++)
                            sp[(mf * 4 + nf) * 4 + c2] = acc[mf][nf][c2];
                #pragma unroll
                for (int mf = 0; mf < 2; mf++)
                    #pragma unroll
                    for (int c2 = 0; c2 < 4; c2++)
                        sp[32 + mf * 4 + c2] = fca[mf][c2];
            }
            __syncthreads();
            if (ks == 0) {
                #pragma unroll
                for (int sl = 0; sl < 3; sl++) {
                    const float* sp = scrS + ((sl * 2 + m2) * 32 + lane) * 40;
                    #pragma unroll
                    for (int mf = 0; mf < 2; mf++)
                        #pragma unroll
                        for (int nf = 0; nf < 4; nf++)
                            #pragma unroll
                            for (int c2 = 0; c2 < 4; c2++)
                                acc[mf][nf][c2] += sp[(mf * 4 + nf) * 4 + c2];
                    #pragma unroll
                    for (int mf = 0; mf < 2; mf++)
                        #pragma unroll
                        for (int c2 = 0; c2 < 4; c2++)
                            fca[mf][c2] += sp[32 + mf * 4 + c2];
                }

                float* crow = cS + l * 64 * 8;
                float* op = out + (size_t)(t - 1) * BATCH * HID;
                #pragma unroll
                for (int mf = 0; mf < 2; mf++) {
                    #pragma unroll
                    for (int rp = 0; rp < 2; rp++) {
                        const int b = m2 * 32 + mf * 16 + rp * 8 + r;
                        const int k = rp * 2;
                        #pragma unroll
                        for (int ug = 0; ug < 2; ug++) {
                            const int u = ug * 4 + a4;
                            float iv = acc[mf][ug * 2 + 0][k + 0] + biasS[l * 32 + ug * 16 + a4 * 2 + 0];
                            float fv = acc[mf][ug * 2 + 0][k + 1] + biasS[l * 32 + ug * 16 + a4 * 2 + 1];
                            float gv = acc[mf][ug * 2 + 1][k + 0] + biasS[l * 32 + ug * 16 + 8 + a4 * 2 + 0];
                            float ov = acc[mf][ug * 2 + 1][k + 1] + biasS[l * 32 + ug * 16 + 8 + a4 * 2 + 1];
                            float cn = sig_(fv) * crow[b * 8 + u] + sig_(iv) * tanhf(gv);
                            crow[b * 8 + u] = cn;
                            hdst[b * HID + j0 + u] = __float2half_rn(sig_(ov) * tanhf(cn));
                        }
                        if (fc_phase) {
                            op[b * HID + j0 + a4 * 2 + 0] = fca[mf][k + 0] + fcbS[a4 * 2 + 0];
                            op[b * HID + j0 + a4 * 2 + 1] = fca[mf][k + 1] + fcbS[a4 * 2 + 1];
                        }
                    }
                }
            }
            gbar_arrive();
            barTarget += NCTA;
        }
    }

    // ===== final FC for t = T-1 (x = h1 written at t=127, parity 1) =====
    {
        gbar_wait(barTarget);
        const __half* xsrc = g_hbuf + (2 + 1) * BATCH * HID;
        const __half* wsrc = g_Wst + (size_t)(0 * NCTA + cta) * 40 * HID;
        float fca[2][4] = {{0,0,0,0},{0,0,0,0}};
        #pragma unroll
        for (int i = 0; i < 2; i++) {
            stage_act(actS + i * ABUFH, xsrc, i * KC, tid);
            stage_w40(wringS + w_stage * WBUFH, wsrc, i * KC, tid);
            w_stage = NX3(w_stage);
            cp_commit();
        }
        #pragma unroll 1
        for (int kc = 0; kc < NKC; kc++) {
            cp_wait<1>();
            __syncthreads();
            if (kc + 2 < NKC) {
                stage_act(actS + (kc + 2) * ABUFH, xsrc, (kc + 2) * KC, tid);
                stage_w40(wringS + w_stage * WBUFH, wsrc, (kc + 2) * KC, tid);
                w_stage = NX3(w_stage);
            }
            cp_commit();
            const unsigned xd = (unsigned)kc * ABUF;
            const unsigned wd = (unsigned)w_cons * WBUF;
            w_cons = NX3(w_cons);
            #pragma unroll
            for (int j = 0; j < 2; j++) {
                const int k16 = ks + j * 4;
                unsigned f0, f1;
                ldsm_x2(f0, f1, fcB0 + wd + k16 * 32);
                #pragma unroll
                for (int mf = 0; mf < 2; mf++) {
                    unsigned a0, a1, a2, a3;
                    ldsm_x4(a0, a1, a2, a3, xbA0[mf] + xd + k16 * 32);
                    hmma(fca[mf], a0, a1, a2, a3, f0, f1);
                }
            }
        }
        __syncthreads();
        if (ks > 0) {
            float* sp = scrS + (((ks - 1) * 2 + m2) * 32 + lane) * 40;
            #pragma unroll
            for (int mf = 0; mf < 2; mf++)
                #pragma unroll
                for (int c2 = 0; c2 < 4; c2++)
                    sp[32 + mf * 4 + c2] = fca[mf][c2];
        }
        __syncthreads();
        if (ks == 0) {
            #pragma unroll
            for (int sl = 0; sl < 3; sl++) {
                const float* sp = scrS + ((sl * 2 + m2) * 32 + lane) * 40;
                #pragma unroll
                for (int mf = 0; mf < 2; mf++)
                    #pragma unroll
                    for (int c2 = 0; c2 < 4; c2++)
                        fca[mf][c2] += sp[32 + mf * 4 + c2];
            }
            float* op = out + (size_t)(TSTEPS - 1) * BATCH * HID;
            #pragma unroll
            for (int mf = 0; mf < 2; mf++)
                #pragma unroll
                for (int rp = 0; rp < 2; rp++) {
                    const int b = m2 * 32 + mf * 16 + rp * 8 + r;
                    const int k = rp * 2;
                    op[b * HID + j0 + a4 * 2 + 0] = fca[mf][k + 0] + fcbS[a4 * 2 + 0];
                    op[b * HID + j0 + a4 * 2 + 1] = fca[mf][k + 1] + fcbS[a4 * 2 + 1];
                }
        }
    }
}

// ---------------- host launch -----------------------------------------------
extern "C" void kernel_launch(void* const* d_in, const int* in_sizes, int n_in,
                              void* d_out, int out_size) {
    const float* h0  = (const float*)d_in[0];
    const float* Wih = (const float*)d_in[1];
    const float* Whh = (const float*)d_in[2];
    const float* bih = (const float*)d_in[3];
    const float* bhh = (const float*)d_in[4];
    const float* Wfc = (const float*)d_in[5];
    const float* bfc = (const float*)d_in[6];
    float* out = (float*)d_out;

    const int smem = (8 * 64 * SA + 3 * 40 * SW) * 2
                   + (6 * 32 * 40 + 2 * 64 * 8 + 64 + 8) * 4;
    cudaFuncSetAttribute(lstm_persist, cudaFuncAttributeMaxDynamicSharedMemorySize, smem);

    prep_all<<<2048, 256>>>(Wih, Whh, h0, Wfc);
    lstm_persist<<<NCTA, THREADS, smem>>>(bih, bhh, bfc, out);
}